// round 14
// baseline (speedup 1.0000x reference)
#include <cuda_runtime.h>

#define NS    512
#define NOBJ  16
#define MPTS  8192
#define HW    16384      // 128*128
#define HW4   (HW / 4)
#define TPB   256
#define NCHUNK (HW4 / TPB)   // 16
#define NBUF  3

typedef unsigned long long u64;

__device__ __forceinline__ u64 pk2(float lo, float hi) {
    u64 r; asm("mov.b64 %0, {%1, %2};" : "=l"(r) : "f"(lo), "f"(hi)); return r;
}
__device__ __forceinline__ void upk2(u64 v, float& lo, float& hi) {
    asm("mov.b64 {%0, %1}, %2;" : "=f"(lo), "=f"(hi) : "l"(v));
}
__device__ __forceinline__ u64 fma2(u64 a, u64 b, u64 c) {
    u64 d; asm("fma.rn.f32x2 %0, %1, %2, %3;" : "=l"(d) : "l"(a), "l"(b), "l"(c)); return d;
}
__device__ __forceinline__ u64 mul2(u64 a, u64 b) {
    u64 d; asm("mul.rn.f32x2 %0, %1, %2;" : "=l"(d) : "l"(a), "l"(b)); return d;
}
__device__ __forceinline__ float rcpa(float x) {
    float r; asm("rcp.approx.f32 %0, %1;" : "=f"(r) : "f"(x)); return r;
}
__device__ __forceinline__ float sqrta(float x) {
    float r; asm("sqrt.approx.f32 %0, %1;" : "=f"(r) : "f"(x)); return r;
}
__device__ __forceinline__ unsigned int s2u(const void* p) {
    unsigned int a;
    asm("{ .reg .u64 t; cvta.to.shared.u64 t, %1; cvt.u32.u64 %0, t; }" : "=r"(a) : "l"(p));
    return a;
}
#define CP16(dst, src) asm volatile("cp.async.cg.shared.global [%0], [%1], 16;" :: "r"(dst), "l"(src))
#define CP_COMMIT()    asm volatile("cp.async.commit_group;")
#define CP_WAIT(N)     asm volatile("cp.async.wait_group %0;" :: "n"(N))

__device__ __forceinline__ float4 lds128f(unsigned int a) {
    float4 v;
    asm volatile("ld.shared.v4.f32 {%0,%1,%2,%3}, [%4];"
                 : "=f"(v.x), "=f"(v.y), "=f"(v.z), "=f"(v.w) : "r"(a));
    return v;
}

// blocks [0, NS)     : pv  (masked projected distance over ROI)  -- BW bound
// blocks [NS, 2*NS)  : re/te/ad/pj (scalars + mesh reductions)   -- fma bound
__global__ __launch_bounds__(TPB, 2) void score_kernel(
    const int*   __restrict__ obj_id,
    const float* __restrict__ cam_K,
    const float* __restrict__ gtR,
    const float* __restrict__ gtT,
    const float* __restrict__ prR,
    const float* __restrict__ prT,
    const float* __restrict__ coord,        // [NS,3,H,W]
    const unsigned int* __restrict__ maskp, // [NS,H,W] nonzero == true
    const float* __restrict__ mesh,         // [NOBJ,MPTS,3]
    const float* __restrict__ diam,
    float*       __restrict__ out)          // [5,NS]
{
    const int tid  = threadIdx.x;
    const bool is_pv = (blockIdx.x < NS);
    const int n   = is_pv ? blockIdx.x : (blockIdx.x - NS);

    __shared__ float4 stage[NBUF][3][TPB];   // X,Y,Z only: 36 KB
    __shared__ u64 sdR[9], sdt[3];
    __shared__ float sInvDiam;
    __shared__ int   sObj;
    __shared__ float redA[8], redB[8];

    // ---- per-thread register coefficients (broadcast pairs) ----
    float K[9], Rp[9], Rg[9], tp[3], tg[3];
#pragma unroll
    for (int k = 0; k < 9; k++) {
        K[k]  = __ldg(cam_K + n * 9 + k);
        Rp[k] = __ldg(prR   + n * 9 + k);
        Rg[k] = __ldg(gtR   + n * 9 + k);
    }
#pragma unroll
    for (int k = 0; k < 3; k++) { tp[k] = __ldg(prT + n*3 + k); tg[k] = __ldg(gtT + n*3 + k); }

    u64 cKp[9], cKg[9], cktp[3], cktg[3];
#pragma unroll
    for (int i = 0; i < 3; i++) {
        float sg = (i < 2) ? -1.0f : 1.0f;   // negate Kg rows 0,1
#pragma unroll
        for (int j = 0; j < 3; j++) {
            float a = K[i*3+0]*Rp[0*3+j] + K[i*3+1]*Rp[1*3+j] + K[i*3+2]*Rp[2*3+j];
            float b = (K[i*3+0]*Rg[0*3+j] + K[i*3+1]*Rg[1*3+j] + K[i*3+2]*Rg[2*3+j]) * sg;
            cKp[i*3+j] = pk2(a, a);
            cKg[i*3+j] = pk2(b, b);
        }
        float a = K[i*3+0]*tp[0] + K[i*3+1]*tp[1] + K[i*3+2]*tp[2];
        float b = (K[i*3+0]*tg[0] + K[i*3+1]*tg[1] + K[i*3+2]*tg[2]) * sg;
        cktp[i] = pk2(a, a);
        cktg[i] = pk2(b, b);
    }

    if (!is_pv && tid == 0) {
#pragma unroll
        for (int k = 0; k < 9; k++) { float d = Rp[k] - Rg[k]; sdR[k] = pk2(d, d); }
#pragma unroll
        for (int k = 0; k < 3; k++) { float d = tp[k] - tg[k]; sdt[k] = pk2(d, d); }
        int obj = obj_id[n];
        sObj = obj;
        sInvDiam = 1.0f / diam[obj];
        float tr = 0.0f;
#pragma unroll
        for (int k = 0; k < 9; k++) tr += Rp[k] * Rg[k];
        float c = fminf(fmaxf(tr, -1.0f), 3.0f);
        out[n] = acosf((c - 1.0f) * 0.5f) * 57.2957795130823209f;
        float dx = tp[0]-tg[0], dy = tp[1]-tg[1], dz = tp[2]-tg[2];
        out[NS + n] = sqrtf(dx*dx + dy*dy + dz*dz) * 100.0f;
    }
    if (!is_pv) __syncthreads();

    float accA = 0.0f, accB = 0.0f;

    if (is_pv) {
        const float4* vx = (const float4*)(coord + (size_t)n * 3 * HW);
        const float4* vy = vx + HW4;
        const float4* vz = vy + HW4;
        const uint4*  mk = (const uint4*)(maskp + (size_t)n * HW);

        unsigned int aX0 = s2u(&stage[0][0][tid]), aY0 = s2u(&stage[0][1][tid]),
                     aZ0 = s2u(&stage[0][2][tid]);
        const unsigned int bstride = (unsigned int)(3 * TPB * sizeof(float4));

        uint4 Mring[NBUF];

        // prologue: issue chunks 0..2 (3 groups in flight) + mask register ring
#pragma unroll
        for (int p = 0; p < NBUF; p++) {
            const int idx = tid + p * TPB;
            const unsigned int off = p * bstride;
            CP16(aX0 + off, vx + idx);
            CP16(aY0 + off, vy + idx);
            CP16(aZ0 + off, vz + idx);
            CP_COMMIT();
            Mring[p] = __ldg(mk + idx);
        }

#pragma unroll
        for (int c = 0; c < NCHUNK; c++) {
            // groups issued so far = min(16, c+3); need group c complete
            if (c <= NCHUNK - 3)      { CP_WAIT(2); }
            else if (c == NCHUNK - 2) { CP_WAIT(1); }
            else                      { CP_WAIT(0); }

            const int slot = c % NBUF;
            const unsigned int off = slot * bstride;
            float4 X = lds128f(aX0 + off);
            float4 Y = lds128f(aY0 + off);
            float4 Z = lds128f(aZ0 + off);
            uint4  Mw = Mring[slot];

            if (c + NBUF < NCHUNK) {
                const int idx = tid + (c + NBUF) * TPB;
                CP16(aX0 + off, vx + idx);
                CP16(aY0 + off, vy + idx);
                CP16(aZ0 + off, vz + idx);
                CP_COMMIT();
                Mring[slot] = __ldg(mk + idx);
            }

#pragma unroll
            for (int half = 0; half < 2; half++) {
                u64 x2 = half ? pk2(X.z, X.w) : pk2(X.x, X.y);
                u64 y2 = half ? pk2(Y.z, Y.w) : pk2(Y.x, Y.y);
                u64 z2 = half ? pk2(Z.z, Z.w) : pk2(Z.x, Z.y);
                unsigned int m0 = half ? Mw.z : Mw.x;
                unsigned int m1 = half ? Mw.w : Mw.y;

                u64 hx  = fma2(cKp[0], x2, fma2(cKp[1], y2, fma2(cKp[2], z2, cktp[0])));
                u64 hy  = fma2(cKp[3], x2, fma2(cKp[4], y2, fma2(cKp[5], z2, cktp[1])));
                u64 hz  = fma2(cKp[6], x2, fma2(cKp[7], y2, fma2(cKp[8], z2, cktp[2])));
                u64 gxn = fma2(cKg[0], x2, fma2(cKg[1], y2, fma2(cKg[2], z2, cktg[0])));
                u64 gyn = fma2(cKg[3], x2, fma2(cKg[4], y2, fma2(cKg[5], z2, cktg[1])));
                u64 gz  = fma2(cKg[6], x2, fma2(cKg[7], y2, fma2(cKg[8], z2, cktg[2])));

                u64 nx = fma2(gxn, hz, mul2(hx, gz));   // hx*gz - gx*hz
                u64 ny = fma2(gyn, hz, mul2(hy, gz));
                u64 dn = mul2(hz, gz);
                float dn0, dn1;
                upk2(dn, dn0, dn1);
                u64 r2 = pk2(rcpa(dn0), rcpa(dn1));
                u64 s2 = mul2(fma2(ny, ny, mul2(nx, nx)), mul2(r2, r2));
                float s0, s1;
                upk2(s2, s0, s1);
                if (m0 != 0u) { accA += sqrta(s0); accB += 1.0f; }
                if (m1 != 0u) { accA += sqrta(s1); accB += 1.0f; }
            }
        }
    } else {
        const float2* pts2 = (const float2*)(mesh + (size_t)sObj * MPTS * 3);
        float2 a0 = __ldg(pts2 + 3*tid + 0);
        float2 b0 = __ldg(pts2 + 3*tid + 1);
        float2 c0 = __ldg(pts2 + 3*tid + 2);
#pragma unroll
        for (int c = 0; c < NCHUNK; c++) {
            float2 a1, b1, c1;
            if (c < NCHUNK - 1) {
                const int t = tid + (c + 1) * TPB;
                a1 = __ldg(pts2 + 3*t + 0);
                b1 = __ldg(pts2 + 3*t + 1);
                c1 = __ldg(pts2 + 3*t + 2);
            } else {
                a1 = a0; b1 = b0; c1 = c0;
            }
            u64 px2 = pk2(a0.x, b0.y);
            u64 py2 = pk2(a0.y, c0.x);
            u64 pz2 = pk2(b0.x, c0.y);

            // ADD
            u64 ax = fma2(sdR[0], px2, fma2(sdR[1], py2, fma2(sdR[2], pz2, sdt[0])));
            u64 ay = fma2(sdR[3], px2, fma2(sdR[4], py2, fma2(sdR[5], pz2, sdt[1])));
            u64 az = fma2(sdR[6], px2, fma2(sdR[7], py2, fma2(sdR[8], pz2, sdt[2])));
            u64 sa = fma2(az, az, fma2(ay, ay, mul2(ax, ax)));
            float sa0, sa1;
            upk2(sa, sa0, sa1);
            accA += sqrta(sa0) + sqrta(sa1);

            // PROJ
            u64 hx  = fma2(cKp[0], px2, fma2(cKp[1], py2, fma2(cKp[2], pz2, cktp[0])));
            u64 hy  = fma2(cKp[3], px2, fma2(cKp[4], py2, fma2(cKp[5], pz2, cktp[1])));
            u64 hz  = fma2(cKp[6], px2, fma2(cKp[7], py2, fma2(cKp[8], pz2, cktp[2])));
            u64 gxn = fma2(cKg[0], px2, fma2(cKg[1], py2, fma2(cKg[2], pz2, cktg[0])));
            u64 gyn = fma2(cKg[3], px2, fma2(cKg[4], py2, fma2(cKg[5], pz2, cktg[1])));
            u64 gz  = fma2(cKg[6], px2, fma2(cKg[7], py2, fma2(cKg[8], pz2, cktg[2])));

            u64 nx = fma2(gxn, hz, mul2(hx, gz));
            u64 ny = fma2(gyn, hz, mul2(hy, gz));
            u64 dn = mul2(hz, gz);
            float dn0, dn1;
            upk2(dn, dn0, dn1);
            u64 r2 = pk2(rcpa(dn0), rcpa(dn1));
            u64 sp = mul2(fma2(ny, ny, mul2(nx, nx)), mul2(r2, r2));
            float sp0, sp1;
            upk2(sp, sp0, sp1);
            accB += sqrta(sp0) + sqrta(sp1);

            a0 = a1; b0 = b1; c0 = c1;
        }
    }

    // block reduce (accA, accB)
    {
        const int lane = tid & 31;
        const int wid  = tid >> 5;
#pragma unroll
        for (int o = 16; o > 0; o >>= 1) {
            accA += __shfl_down_sync(0xffffffffu, accA, o);
            accB += __shfl_down_sync(0xffffffffu, accB, o);
        }
        if (lane == 0) { redA[wid] = accA; redB[wid] = accB; }
        __syncthreads();
        if (wid == 0) {
            accA = (lane < (TPB / 32)) ? redA[lane] : 0.0f;
            accB = (lane < (TPB / 32)) ? redB[lane] : 0.0f;
#pragma unroll
            for (int o = 4; o > 0; o >>= 1) {
                accA += __shfl_down_sync(0xffffffffu, accA, o);
                accB += __shfl_down_sync(0xffffffffu, accB, o);
            }
            if (lane == 0) {
                if (is_pv) {
                    out[4 * NS + n] = accA / fmaxf(accB, 1.0f);
                } else {
                    out[2 * NS + n] = accA * (1.0f / MPTS) * sInvDiam;
                    out[3 * NS + n] = accB * (1.0f / MPTS);
                }
            }
        }
    }
}

extern "C" void kernel_launch(void* const* d_in, const int* in_sizes, int n_in,
                              void* d_out, int out_size) {
    const int*   obj_id = (const int*)  d_in[0];
    const float* cam_K  = (const float*)d_in[1];
    const float* gtR    = (const float*)d_in[2];
    const float* gtT    = (const float*)d_in[3];
    const float* prR    = (const float*)d_in[4];
    const float* prT    = (const float*)d_in[5];
    const float* coord  = (const float*)d_in[6];
    const unsigned int* maskp = (const unsigned int*)d_in[7];
    const float* mesh   = (const float*)d_in[8];
    const float* diam   = (const float*)d_in[9];
    float* out = (float*)d_out;

    score_kernel<<<2 * NS, TPB>>>(obj_id, cam_K, gtR, gtT, prR, prT,
                                  coord, maskp, mesh, diam, out);
}

// round 15
// speedup vs baseline: 1.1997x; 1.1997x over previous
#include <cuda_runtime.h>

#define NS    512
#define NOBJ  16
#define MPTS  8192
#define HW    16384      // 128*128
#define HW4   (HW / 4)
#define TPB   256
#define NCHUNK (HW4 / TPB)   // 16
#define NBUF  4
#define STAGE_BYTES 16384            // 4 arrays * 4KB
#define CHUNK_ARR_BYTES 4096         // TPB * 16
#define DYN_SMEM (NBUF * STAGE_BYTES)

typedef unsigned long long u64;

__device__ __forceinline__ u64 pk2(float lo, float hi) {
    u64 r; asm("mov.b64 %0, {%1, %2};" : "=l"(r) : "f"(lo), "f"(hi)); return r;
}
__device__ __forceinline__ void upk2(u64 v, float& lo, float& hi) {
    asm("mov.b64 {%0, %1}, %2;" : "=f"(lo), "=f"(hi) : "l"(v));
}
__device__ __forceinline__ u64 fma2(u64 a, u64 b, u64 c) {
    u64 d; asm("fma.rn.f32x2 %0, %1, %2, %3;" : "=l"(d) : "l"(a), "l"(b), "l"(c)); return d;
}
__device__ __forceinline__ u64 mul2(u64 a, u64 b) {
    u64 d; asm("mul.rn.f32x2 %0, %1, %2;" : "=l"(d) : "l"(a), "l"(b)); return d;
}
__device__ __forceinline__ float rcpa(float x) {
    float r; asm("rcp.approx.f32 %0, %1;" : "=f"(r) : "f"(x)); return r;
}
__device__ __forceinline__ float sqrta(float x) {
    float r; asm("sqrt.approx.f32 %0, %1;" : "=f"(r) : "f"(x)); return r;
}
__device__ __forceinline__ unsigned int s2u(const void* p) {
    unsigned int a;
    asm("{ .reg .u64 t; cvta.to.shared.u64 t, %1; cvt.u32.u64 %0, t; }" : "=r"(a) : "l"(p));
    return a;
}
__device__ __forceinline__ float4 lds128f(unsigned int a) {
    float4 v;
    asm volatile("ld.shared.v4.f32 {%0,%1,%2,%3}, [%4];"
                 : "=f"(v.x), "=f"(v.y), "=f"(v.z), "=f"(v.w) : "r"(a));
    return v;
}
__device__ __forceinline__ uint4 lds128u(unsigned int a) {
    uint4 v;
    asm volatile("ld.shared.v4.u32 {%0,%1,%2,%3}, [%4];"
                 : "=r"(v.x), "=r"(v.y), "=r"(v.z), "=r"(v.w) : "r"(a));
    return v;
}
#define MBAR_INIT(addr, cnt) \
    asm volatile("mbarrier.init.shared.b64 [%0], %1;" :: "r"(addr), "r"(cnt) : "memory")
#define MBAR_EXPECT_TX(addr, bytes) \
    asm volatile("mbarrier.arrive.expect_tx.shared.b64 _, [%0], %1;" :: "r"(addr), "r"(bytes) : "memory")
#define BULK_CP(dst, src, sz, mbar) \
    asm volatile("cp.async.bulk.shared::cta.global.mbarrier::complete_tx::bytes [%0], [%1], %2, [%3];" \
                 :: "r"(dst), "l"(src), "r"(sz), "r"(mbar) : "memory")
#define MBAR_WAIT(addr, parity) do { \
    asm volatile("{\n\t.reg .pred P;\n\tWL_%=:\n\t" \
                 "mbarrier.try_wait.parity.acquire.cta.shared::cta.b64 P, [%0], %1;\n\t" \
                 "@!P bra WL_%=;\n\t}" :: "r"(addr), "r"(parity) : "memory"); \
} while (0)

// blocks [0, NS)     : pv  (masked projected distance over ROI)  -- TMA-staged, BW bound
// blocks [NS, 2*NS)  : re/te/ad/pj (scalars + mesh reductions)   -- fma bound
__global__ __launch_bounds__(TPB, 2) void score_kernel(
    const int*   __restrict__ obj_id,
    const float* __restrict__ cam_K,
    const float* __restrict__ gtR,
    const float* __restrict__ gtT,
    const float* __restrict__ prR,
    const float* __restrict__ prT,
    const float* __restrict__ coord,        // [NS,3,H,W]
    const unsigned int* __restrict__ maskp, // [NS,H,W] nonzero == true
    const float* __restrict__ mesh,         // [NOBJ,MPTS,3]
    const float* __restrict__ diam,
    float*       __restrict__ out)          // [5,NS]
{
    extern __shared__ float4 dynstage[];    // [NBUF][4][TPB] float4

    const int tid  = threadIdx.x;
    const bool is_pv = (blockIdx.x < NS);
    const int n   = is_pv ? blockIdx.x : (blockIdx.x - NS);

    __shared__ u64 smbar[NBUF];
    __shared__ u64 sdR[9], sdt[3];
    __shared__ float sInvDiam;
    __shared__ int   sObj;
    __shared__ float redA[8], redB[8];

    // ---- per-thread register coefficients (broadcast pairs) ----
    float K[9], Rp[9], Rg[9], tp[3], tg[3];
#pragma unroll
    for (int k = 0; k < 9; k++) {
        K[k]  = __ldg(cam_K + n * 9 + k);
        Rp[k] = __ldg(prR   + n * 9 + k);
        Rg[k] = __ldg(gtR   + n * 9 + k);
    }
#pragma unroll
    for (int k = 0; k < 3; k++) { tp[k] = __ldg(prT + n*3 + k); tg[k] = __ldg(gtT + n*3 + k); }

    u64 cKp[9], cKg[9], cktp[3], cktg[3];
#pragma unroll
    for (int i = 0; i < 3; i++) {
        float sg = (i < 2) ? -1.0f : 1.0f;   // negate Kg rows 0,1
#pragma unroll
        for (int j = 0; j < 3; j++) {
            float a = K[i*3+0]*Rp[0*3+j] + K[i*3+1]*Rp[1*3+j] + K[i*3+2]*Rp[2*3+j];
            float b = (K[i*3+0]*Rg[0*3+j] + K[i*3+1]*Rg[1*3+j] + K[i*3+2]*Rg[2*3+j]) * sg;
            cKp[i*3+j] = pk2(a, a);
            cKg[i*3+j] = pk2(b, b);
        }
        float a = K[i*3+0]*tp[0] + K[i*3+1]*tp[1] + K[i*3+2]*tp[2];
        float b = (K[i*3+0]*tg[0] + K[i*3+1]*tg[1] + K[i*3+2]*tg[2]) * sg;
        cktp[i] = pk2(a, a);
        cktg[i] = pk2(b, b);
    }

    if (!is_pv && tid == 0) {
#pragma unroll
        for (int k = 0; k < 9; k++) { float d = Rp[k] - Rg[k]; sdR[k] = pk2(d, d); }
#pragma unroll
        for (int k = 0; k < 3; k++) { float d = tp[k] - tg[k]; sdt[k] = pk2(d, d); }
        int obj = obj_id[n];
        sObj = obj;
        sInvDiam = 1.0f / diam[obj];
        float tr = 0.0f;
#pragma unroll
        for (int k = 0; k < 9; k++) tr += Rp[k] * Rg[k];
        float c = fminf(fmaxf(tr, -1.0f), 3.0f);
        out[n] = acosf((c - 1.0f) * 0.5f) * 57.2957795130823209f;
        float dx = tp[0]-tg[0], dy = tp[1]-tg[1], dz = tp[2]-tg[2];
        out[NS + n] = sqrtf(dx*dx + dy*dy + dz*dz) * 100.0f;
    }
    if (!is_pv) __syncthreads();

    float accA = 0.0f, accB = 0.0f;

    if (is_pv) {
        const char* px = (const char*)(coord + (size_t)n * 3 * HW);            // x plane
        const char* py = px + HW * 4;                                          // y plane
        const char* pz = py + HW * 4;                                          // z plane
        const char* pm = (const char*)(maskp + (size_t)n * HW);                // mask plane

        const unsigned int stBase = s2u(dynstage);
        const unsigned int mb0    = s2u(&smbar[0]);

        if (tid == 0) {
#pragma unroll
            for (int s = 0; s < NBUF; s++) MBAR_INIT(mb0 + s * 8, 1);
        }
        __syncthreads();

        // prologue: issue chunks 0..3
        if (tid == 0) {
#pragma unroll
            for (int p = 0; p < NBUF; p++) {
                const unsigned int mb = mb0 + p * 8;
                const unsigned int st = stBase + p * STAGE_BYTES;
                const size_t go = (size_t)p * CHUNK_ARR_BYTES;
                MBAR_EXPECT_TX(mb, STAGE_BYTES);
                BULK_CP(st,                        px + go, CHUNK_ARR_BYTES, mb);
                BULK_CP(st + 1 * CHUNK_ARR_BYTES,  py + go, CHUNK_ARR_BYTES, mb);
                BULK_CP(st + 2 * CHUNK_ARR_BYTES,  pz + go, CHUNK_ARR_BYTES, mb);
                BULK_CP(st + 3 * CHUNK_ARR_BYTES,  pm + go, CHUNK_ARR_BYTES, mb);
            }
        }

#pragma unroll
        for (int c = 0; c < NCHUNK; c++) {
            const int slot = c & (NBUF - 1);
            const unsigned int mb = mb0 + slot * 8;
            const unsigned int st = stBase + slot * STAGE_BYTES + tid * 16;
            MBAR_WAIT(mb, (c >> 2) & 1);

            float4 X = lds128f(st);
            float4 Y = lds128f(st + 1 * CHUNK_ARR_BYTES);
            float4 Z = lds128f(st + 2 * CHUNK_ARR_BYTES);
            uint4  Mw = lds128u(st + 3 * CHUNK_ARR_BYTES);

            __syncthreads();   // whole block done reading this slot
            if (tid == 0 && c + NBUF < NCHUNK) {
                const unsigned int stp = stBase + slot * STAGE_BYTES;
                const size_t go = (size_t)(c + NBUF) * CHUNK_ARR_BYTES;
                MBAR_EXPECT_TX(mb, STAGE_BYTES);
                BULK_CP(stp,                       px + go, CHUNK_ARR_BYTES, mb);
                BULK_CP(stp + 1 * CHUNK_ARR_BYTES, py + go, CHUNK_ARR_BYTES, mb);
                BULK_CP(stp + 2 * CHUNK_ARR_BYTES, pz + go, CHUNK_ARR_BYTES, mb);
                BULK_CP(stp + 3 * CHUNK_ARR_BYTES, pm + go, CHUNK_ARR_BYTES, mb);
            }

#pragma unroll
            for (int half = 0; half < 2; half++) {
                u64 x2 = half ? pk2(X.z, X.w) : pk2(X.x, X.y);
                u64 y2 = half ? pk2(Y.z, Y.w) : pk2(Y.x, Y.y);
                u64 z2 = half ? pk2(Z.z, Z.w) : pk2(Z.x, Z.y);
                unsigned int m0 = half ? Mw.z : Mw.x;
                unsigned int m1 = half ? Mw.w : Mw.y;

                u64 hx  = fma2(cKp[0], x2, fma2(cKp[1], y2, fma2(cKp[2], z2, cktp[0])));
                u64 hy  = fma2(cKp[3], x2, fma2(cKp[4], y2, fma2(cKp[5], z2, cktp[1])));
                u64 hz  = fma2(cKp[6], x2, fma2(cKp[7], y2, fma2(cKp[8], z2, cktp[2])));
                u64 gxn = fma2(cKg[0], x2, fma2(cKg[1], y2, fma2(cKg[2], z2, cktg[0])));
                u64 gyn = fma2(cKg[3], x2, fma2(cKg[4], y2, fma2(cKg[5], z2, cktg[1])));
                u64 gz  = fma2(cKg[6], x2, fma2(cKg[7], y2, fma2(cKg[8], z2, cktg[2])));

                u64 nx = fma2(gxn, hz, mul2(hx, gz));   // hx*gz - gx*hz
                u64 ny = fma2(gyn, hz, mul2(hy, gz));
                u64 dn = mul2(hz, gz);
                float dn0, dn1;
                upk2(dn, dn0, dn1);
                u64 r2 = pk2(rcpa(dn0), rcpa(dn1));
                u64 s2 = mul2(fma2(ny, ny, mul2(nx, nx)), mul2(r2, r2));
                float s0, s1;
                upk2(s2, s0, s1);
                if (m0 != 0u) { accA += sqrta(s0); accB += 1.0f; }
                if (m1 != 0u) { accA += sqrta(s1); accB += 1.0f; }
            }
        }
    } else {
        const float2* pts2 = (const float2*)(mesh + (size_t)sObj * MPTS * 3);
        float2 a0 = __ldg(pts2 + 3*tid + 0);
        float2 b0 = __ldg(pts2 + 3*tid + 1);
        float2 c0 = __ldg(pts2 + 3*tid + 2);
#pragma unroll
        for (int c = 0; c < NCHUNK; c++) {
            float2 a1, b1, c1;
            if (c < NCHUNK - 1) {
                const int t = tid + (c + 1) * TPB;
                a1 = __ldg(pts2 + 3*t + 0);
                b1 = __ldg(pts2 + 3*t + 1);
                c1 = __ldg(pts2 + 3*t + 2);
            } else {
                a1 = a0; b1 = b0; c1 = c0;
            }
            u64 px2 = pk2(a0.x, b0.y);
            u64 py2 = pk2(a0.y, c0.x);
            u64 pz2 = pk2(b0.x, c0.y);

            // ADD
            u64 ax = fma2(sdR[0], px2, fma2(sdR[1], py2, fma2(sdR[2], pz2, sdt[0])));
            u64 ay = fma2(sdR[3], px2, fma2(sdR[4], py2, fma2(sdR[5], pz2, sdt[1])));
            u64 az = fma2(sdR[6], px2, fma2(sdR[7], py2, fma2(sdR[8], pz2, sdt[2])));
            u64 sa = fma2(az, az, fma2(ay, ay, mul2(ax, ax)));
            float sa0, sa1;
            upk2(sa, sa0, sa1);
            accA += sqrta(sa0) + sqrta(sa1);

            // PROJ
            u64 hx  = fma2(cKp[0], px2, fma2(cKp[1], py2, fma2(cKp[2], pz2, cktp[0])));
            u64 hy  = fma2(cKp[3], px2, fma2(cKp[4], py2, fma2(cKp[5], pz2, cktp[1])));
            u64 hz  = fma2(cKp[6], px2, fma2(cKp[7], py2, fma2(cKp[8], pz2, cktp[2])));
            u64 gxn = fma2(cKg[0], px2, fma2(cKg[1], py2, fma2(cKg[2], pz2, cktg[0])));
            u64 gyn = fma2(cKg[3], px2, fma2(cKg[4], py2, fma2(cKg[5], pz2, cktg[1])));
            u64 gz  = fma2(cKg[6], px2, fma2(cKg[7], py2, fma2(cKg[8], pz2, cktg[2])));

            u64 nx = fma2(gxn, hz, mul2(hx, gz));
            u64 ny = fma2(gyn, hz, mul2(hy, gz));
            u64 dn = mul2(hz, gz);
            float dn0, dn1;
            upk2(dn, dn0, dn1);
            u64 r2 = pk2(rcpa(dn0), rcpa(dn1));
            u64 sp = mul2(fma2(ny, ny, mul2(nx, nx)), mul2(r2, r2));
            float sp0, sp1;
            upk2(sp, sp0, sp1);
            accB += sqrta(sp0) + sqrta(sp1);

            a0 = a1; b0 = b1; c0 = c1;
        }
    }

    // block reduce (accA, accB)
    {
        const int lane = tid & 31;
        const int wid  = tid >> 5;
#pragma unroll
        for (int o = 16; o > 0; o >>= 1) {
            accA += __shfl_down_sync(0xffffffffu, accA, o);
            accB += __shfl_down_sync(0xffffffffu, accB, o);
        }
        if (lane == 0) { redA[wid] = accA; redB[wid] = accB; }
        __syncthreads();
        if (wid == 0) {
            accA = (lane < (TPB / 32)) ? redA[lane] : 0.0f;
            accB = (lane < (TPB / 32)) ? redB[lane] : 0.0f;
#pragma unroll
            for (int o = 4; o > 0; o >>= 1) {
                accA += __shfl_down_sync(0xffffffffu, accA, o);
                accB += __shfl_down_sync(0xffffffffu, accB, o);
            }
            if (lane == 0) {
                if (is_pv) {
                    out[4 * NS + n] = accA / fmaxf(accB, 1.0f);
                } else {
                    out[2 * NS + n] = accA * (1.0f / MPTS) * sInvDiam;
                    out[3 * NS + n] = accB * (1.0f / MPTS);
                }
            }
        }
    }
}

extern "C" void kernel_launch(void* const* d_in, const int* in_sizes, int n_in,
                              void* d_out, int out_size) {
    const int*   obj_id = (const int*)  d_in[0];
    const float* cam_K  = (const float*)d_in[1];
    const float* gtR    = (const float*)d_in[2];
    const float* gtT    = (const float*)d_in[3];
    const float* prR    = (const float*)d_in[4];
    const float* prT    = (const float*)d_in[5];
    const float* coord  = (const float*)d_in[6];
    const unsigned int* maskp = (const unsigned int*)d_in[7];
    const float* mesh   = (const float*)d_in[8];
    const float* diam   = (const float*)d_in[9];
    float* out = (float*)d_out;

    cudaFuncSetAttribute(score_kernel, cudaFuncAttributeMaxDynamicSharedMemorySize, DYN_SMEM);
    score_kernel<<<2 * NS, TPB, DYN_SMEM>>>(obj_id, cam_K, gtR, gtT, prR, prT,
                                            coord, maskp, mesh, diam, out);
}

// round 16
// speedup vs baseline: 1.2141x; 1.0120x over previous
#include <cuda_runtime.h>

#define NS    512
#define NOBJ  16
#define MPTS  8192
#define HW    16384      // 128*128
#define HW4   (HW / 4)
#define TPB   256
#define NCHUNK (HW4 / TPB)   // 16
#define NBUF  4
#define STAGE_BYTES 16384            // 4 arrays * 4KB
#define CHUNK_ARR_BYTES 4096         // TPB * 16
#define DYN_SMEM (NBUF * STAGE_BYTES)

typedef unsigned long long u64;

__device__ __forceinline__ u64 pk2(float lo, float hi) {
    u64 r; asm("mov.b64 %0, {%1, %2};" : "=l"(r) : "f"(lo), "f"(hi)); return r;
}
__device__ __forceinline__ void upk2(u64 v, float& lo, float& hi) {
    asm("mov.b64 {%0, %1}, %2;" : "=f"(lo), "=f"(hi) : "l"(v));
}
__device__ __forceinline__ u64 fma2(u64 a, u64 b, u64 c) {
    u64 d; asm("fma.rn.f32x2 %0, %1, %2, %3;" : "=l"(d) : "l"(a), "l"(b), "l"(c)); return d;
}
__device__ __forceinline__ u64 mul2(u64 a, u64 b) {
    u64 d; asm("mul.rn.f32x2 %0, %1, %2;" : "=l"(d) : "l"(a), "l"(b)); return d;
}
__device__ __forceinline__ float rcpa(float x) {
    float r; asm("rcp.approx.f32 %0, %1;" : "=f"(r) : "f"(x)); return r;
}
__device__ __forceinline__ float sqrta(float x) {
    float r; asm("sqrt.approx.f32 %0, %1;" : "=f"(r) : "f"(x)); return r;
}
__device__ __forceinline__ unsigned int s2u(const void* p) {
    unsigned int a;
    asm("{ .reg .u64 t; cvta.to.shared.u64 t, %1; cvt.u32.u64 %0, t; }" : "=r"(a) : "l"(p));
    return a;
}
__device__ __forceinline__ float4 lds128f(unsigned int a) {
    float4 v;
    asm volatile("ld.shared.v4.f32 {%0,%1,%2,%3}, [%4];"
                 : "=f"(v.x), "=f"(v.y), "=f"(v.z), "=f"(v.w) : "r"(a));
    return v;
}
__device__ __forceinline__ uint4 lds128u(unsigned int a) {
    uint4 v;
    asm volatile("ld.shared.v4.u32 {%0,%1,%2,%3}, [%4];"
                 : "=r"(v.x), "=r"(v.y), "=r"(v.z), "=r"(v.w) : "r"(a));
    return v;
}
#define MBAR_INIT(addr, cnt) \
    asm volatile("mbarrier.init.shared.b64 [%0], %1;" :: "r"(addr), "r"(cnt) : "memory")
#define MBAR_EXPECT_TX(addr, bytes) \
    asm volatile("mbarrier.arrive.expect_tx.shared.b64 _, [%0], %1;" :: "r"(addr), "r"(bytes) : "memory")
#define BULK_CP(dst, src, sz, mbar) \
    asm volatile("cp.async.bulk.shared::cta.global.mbarrier::complete_tx::bytes [%0], [%1], %2, [%3];" \
                 :: "r"(dst), "l"(src), "r"(sz), "r"(mbar) : "memory")
#define MBAR_WAIT(addr, parity) do { \
    asm volatile("{\n\t.reg .pred P;\n\tWL_%=:\n\t" \
                 "mbarrier.try_wait.parity.acquire.cta.shared::cta.b64 P, [%0], %1;\n\t" \
                 "@!P bra WL_%=;\n\t}" :: "r"(addr), "r"(parity) : "memory"); \
} while (0)

// INTERLEAVED roles: even blocks = pv (DRAM-bound), odd blocks = mesh (compute-bound).
// Each scheduling wave mixes both -> mesh compute hides pv memory latency and
// DRAM is pulled across the whole kernel duration instead of a pv-only phase.
__global__ __launch_bounds__(TPB, 2) void score_kernel(
    const int*   __restrict__ obj_id,
    const float* __restrict__ cam_K,
    const float* __restrict__ gtR,
    const float* __restrict__ gtT,
    const float* __restrict__ prR,
    const float* __restrict__ prT,
    const float* __restrict__ coord,        // [NS,3,H,W]
    const unsigned int* __restrict__ maskp, // [NS,H,W] nonzero == true
    const float* __restrict__ mesh,         // [NOBJ,MPTS,3]
    const float* __restrict__ diam,
    float*       __restrict__ out)          // [5,NS]
{
    extern __shared__ float4 dynstage[];    // [NBUF][4][TPB] float4

    const int tid  = threadIdx.x;
    const bool is_pv = (blockIdx.x & 1) == 0;
    const int n   = blockIdx.x >> 1;

    __shared__ u64 smbar[NBUF];
    __shared__ u64 sdR[9], sdt[3];
    __shared__ float sInvDiam;
    __shared__ int   sObj;
    __shared__ float redA[8], redB[8];

    // ---- per-thread register coefficients (broadcast pairs) ----
    float K[9], Rp[9], Rg[9], tp[3], tg[3];
#pragma unroll
    for (int k = 0; k < 9; k++) {
        K[k]  = __ldg(cam_K + n * 9 + k);
        Rp[k] = __ldg(prR   + n * 9 + k);
        Rg[k] = __ldg(gtR   + n * 9 + k);
    }
#pragma unroll
    for (int k = 0; k < 3; k++) { tp[k] = __ldg(prT + n*3 + k); tg[k] = __ldg(gtT + n*3 + k); }

    u64 cKp[9], cKg[9], cktp[3], cktg[3];
#pragma unroll
    for (int i = 0; i < 3; i++) {
        float sg = (i < 2) ? -1.0f : 1.0f;   // negate Kg rows 0,1
#pragma unroll
        for (int j = 0; j < 3; j++) {
            float a = K[i*3+0]*Rp[0*3+j] + K[i*3+1]*Rp[1*3+j] + K[i*3+2]*Rp[2*3+j];
            float b = (K[i*3+0]*Rg[0*3+j] + K[i*3+1]*Rg[1*3+j] + K[i*3+2]*Rg[2*3+j]) * sg;
            cKp[i*3+j] = pk2(a, a);
            cKg[i*3+j] = pk2(b, b);
        }
        float a = K[i*3+0]*tp[0] + K[i*3+1]*tp[1] + K[i*3+2]*tp[2];
        float b = (K[i*3+0]*tg[0] + K[i*3+1]*tg[1] + K[i*3+2]*tg[2]) * sg;
        cktp[i] = pk2(a, a);
        cktg[i] = pk2(b, b);
    }

    if (!is_pv && tid == 0) {
#pragma unroll
        for (int k = 0; k < 9; k++) { float d = Rp[k] - Rg[k]; sdR[k] = pk2(d, d); }
#pragma unroll
        for (int k = 0; k < 3; k++) { float d = tp[k] - tg[k]; sdt[k] = pk2(d, d); }
        int obj = obj_id[n];
        sObj = obj;
        sInvDiam = 1.0f / diam[obj];
        float tr = 0.0f;
#pragma unroll
        for (int k = 0; k < 9; k++) tr += Rp[k] * Rg[k];
        float c = fminf(fmaxf(tr, -1.0f), 3.0f);
        out[n] = acosf((c - 1.0f) * 0.5f) * 57.2957795130823209f;
        float dx = tp[0]-tg[0], dy = tp[1]-tg[1], dz = tp[2]-tg[2];
        out[NS + n] = sqrtf(dx*dx + dy*dy + dz*dz) * 100.0f;
    }
    if (!is_pv) __syncthreads();

    float accA = 0.0f, accB = 0.0f;

    if (is_pv) {
        const char* px = (const char*)(coord + (size_t)n * 3 * HW);            // x plane
        const char* py = px + HW * 4;                                          // y plane
        const char* pz = py + HW * 4;                                          // z plane
        const char* pm = (const char*)(maskp + (size_t)n * HW);                // mask plane

        const unsigned int stBase = s2u(dynstage);
        const unsigned int mb0    = s2u(&smbar[0]);

        if (tid == 0) {
#pragma unroll
            for (int s = 0; s < NBUF; s++) MBAR_INIT(mb0 + s * 8, 1);
        }
        __syncthreads();

        // prologue: issue chunks 0..3
        if (tid == 0) {
#pragma unroll
            for (int p = 0; p < NBUF; p++) {
                const unsigned int mb = mb0 + p * 8;
                const unsigned int st = stBase + p * STAGE_BYTES;
                const size_t go = (size_t)p * CHUNK_ARR_BYTES;
                MBAR_EXPECT_TX(mb, STAGE_BYTES);
                BULK_CP(st,                        px + go, CHUNK_ARR_BYTES, mb);
                BULK_CP(st + 1 * CHUNK_ARR_BYTES,  py + go, CHUNK_ARR_BYTES, mb);
                BULK_CP(st + 2 * CHUNK_ARR_BYTES,  pz + go, CHUNK_ARR_BYTES, mb);
                BULK_CP(st + 3 * CHUNK_ARR_BYTES,  pm + go, CHUNK_ARR_BYTES, mb);
            }
        }

#pragma unroll
        for (int c = 0; c < NCHUNK; c++) {
            const int slot = c & (NBUF - 1);
            const unsigned int mb = mb0 + slot * 8;
            const unsigned int st = stBase + slot * STAGE_BYTES + tid * 16;
            MBAR_WAIT(mb, (c >> 2) & 1);

            float4 X = lds128f(st);
            float4 Y = lds128f(st + 1 * CHUNK_ARR_BYTES);
            float4 Z = lds128f(st + 2 * CHUNK_ARR_BYTES);
            uint4  Mw = lds128u(st + 3 * CHUNK_ARR_BYTES);

            __syncthreads();   // whole block done reading this slot
            if (tid == 0 && c + NBUF < NCHUNK) {
                const unsigned int stp = stBase + slot * STAGE_BYTES;
                const size_t go = (size_t)(c + NBUF) * CHUNK_ARR_BYTES;
                MBAR_EXPECT_TX(mb, STAGE_BYTES);
                BULK_CP(stp,                       px + go, CHUNK_ARR_BYTES, mb);
                BULK_CP(stp + 1 * CHUNK_ARR_BYTES, py + go, CHUNK_ARR_BYTES, mb);
                BULK_CP(stp + 2 * CHUNK_ARR_BYTES, pz + go, CHUNK_ARR_BYTES, mb);
                BULK_CP(stp + 3 * CHUNK_ARR_BYTES, pm + go, CHUNK_ARR_BYTES, mb);
            }

#pragma unroll
            for (int half = 0; half < 2; half++) {
                u64 x2 = half ? pk2(X.z, X.w) : pk2(X.x, X.y);
                u64 y2 = half ? pk2(Y.z, Y.w) : pk2(Y.x, Y.y);
                u64 z2 = half ? pk2(Z.z, Z.w) : pk2(Z.x, Z.y);
                unsigned int m0 = half ? Mw.z : Mw.x;
                unsigned int m1 = half ? Mw.w : Mw.y;

                u64 hx  = fma2(cKp[0], x2, fma2(cKp[1], y2, fma2(cKp[2], z2, cktp[0])));
                u64 hy  = fma2(cKp[3], x2, fma2(cKp[4], y2, fma2(cKp[5], z2, cktp[1])));
                u64 hz  = fma2(cKp[6], x2, fma2(cKp[7], y2, fma2(cKp[8], z2, cktp[2])));
                u64 gxn = fma2(cKg[0], x2, fma2(cKg[1], y2, fma2(cKg[2], z2, cktg[0])));
                u64 gyn = fma2(cKg[3], x2, fma2(cKg[4], y2, fma2(cKg[5], z2, cktg[1])));
                u64 gz  = fma2(cKg[6], x2, fma2(cKg[7], y2, fma2(cKg[8], z2, cktg[2])));

                u64 nx = fma2(gxn, hz, mul2(hx, gz));   // hx*gz - gx*hz
                u64 ny = fma2(gyn, hz, mul2(hy, gz));
                u64 dn = mul2(hz, gz);
                float dn0, dn1;
                upk2(dn, dn0, dn1);
                u64 r2 = pk2(rcpa(dn0), rcpa(dn1));
                u64 s2 = mul2(fma2(ny, ny, mul2(nx, nx)), mul2(r2, r2));
                float s0, s1;
                upk2(s2, s0, s1);
                if (m0 != 0u) { accA += sqrta(s0); accB += 1.0f; }
                if (m1 != 0u) { accA += sqrta(s1); accB += 1.0f; }
            }
        }
    } else {
        const float2* pts2 = (const float2*)(mesh + (size_t)sObj * MPTS * 3);
        float2 a0 = __ldg(pts2 + 3*tid + 0);
        float2 b0 = __ldg(pts2 + 3*tid + 1);
        float2 c0 = __ldg(pts2 + 3*tid + 2);
#pragma unroll
        for (int c = 0; c < NCHUNK; c++) {
            float2 a1, b1, c1;
            if (c < NCHUNK - 1) {
                const int t = tid + (c + 1) * TPB;
                a1 = __ldg(pts2 + 3*t + 0);
                b1 = __ldg(pts2 + 3*t + 1);
                c1 = __ldg(pts2 + 3*t + 2);
            } else {
                a1 = a0; b1 = b0; c1 = c0;
            }
            u64 px2 = pk2(a0.x, b0.y);
            u64 py2 = pk2(a0.y, c0.x);
            u64 pz2 = pk2(b0.x, c0.y);

            // ADD
            u64 ax = fma2(sdR[0], px2, fma2(sdR[1], py2, fma2(sdR[2], pz2, sdt[0])));
            u64 ay = fma2(sdR[3], px2, fma2(sdR[4], py2, fma2(sdR[5], pz2, sdt[1])));
            u64 az = fma2(sdR[6], px2, fma2(sdR[7], py2, fma2(sdR[8], pz2, sdt[2])));
            u64 sa = fma2(az, az, fma2(ay, ay, mul2(ax, ax)));
            float sa0, sa1;
            upk2(sa, sa0, sa1);
            accA += sqrta(sa0) + sqrta(sa1);

            // PROJ
            u64 hx  = fma2(cKp[0], px2, fma2(cKp[1], py2, fma2(cKp[2], pz2, cktp[0])));
            u64 hy  = fma2(cKp[3], px2, fma2(cKp[4], py2, fma2(cKp[5], pz2, cktp[1])));
            u64 hz  = fma2(cKp[6], px2, fma2(cKp[7], py2, fma2(cKp[8], pz2, cktp[2])));
            u64 gxn = fma2(cKg[0], px2, fma2(cKg[1], py2, fma2(cKg[2], pz2, cktg[0])));
            u64 gyn = fma2(cKg[3], px2, fma2(cKg[4], py2, fma2(cKg[5], pz2, cktg[1])));
            u64 gz  = fma2(cKg[6], px2, fma2(cKg[7], py2, fma2(cKg[8], pz2, cktg[2])));

            u64 nx = fma2(gxn, hz, mul2(hx, gz));
            u64 ny = fma2(gyn, hz, mul2(hy, gz));
            u64 dn = mul2(hz, gz);
            float dn0, dn1;
            upk2(dn, dn0, dn1);
            u64 r2 = pk2(rcpa(dn0), rcpa(dn1));
            u64 sp = mul2(fma2(ny, ny, mul2(nx, nx)), mul2(r2, r2));
            float sp0, sp1;
            upk2(sp, sp0, sp1);
            accB += sqrta(sp0) + sqrta(sp1);

            a0 = a1; b0 = b1; c0 = c1;
        }
    }

    // block reduce (accA, accB)
    {
        const int lane = tid & 31;
        const int wid  = tid >> 5;
#pragma unroll
        for (int o = 16; o > 0; o >>= 1) {
            accA += __shfl_down_sync(0xffffffffu, accA, o);
            accB += __shfl_down_sync(0xffffffffu, accB, o);
        }
        if (lane == 0) { redA[wid] = accA; redB[wid] = accB; }
        __syncthreads();
        if (wid == 0) {
            accA = (lane < (TPB / 32)) ? redA[lane] : 0.0f;
            accB = (lane < (TPB / 32)) ? redB[lane] : 0.0f;
#pragma unroll
            for (int o = 4; o > 0; o >>= 1) {
                accA += __shfl_down_sync(0xffffffffu, accA, o);
                accB += __shfl_down_sync(0xffffffffu, accB, o);
            }
            if (lane == 0) {
                if (is_pv) {
                    out[4 * NS + n] = accA / fmaxf(accB, 1.0f);
                } else {
                    out[2 * NS + n] = accA * (1.0f / MPTS) * sInvDiam;
                    out[3 * NS + n] = accB * (1.0f / MPTS);
                }
            }
        }
    }
}

extern "C" void kernel_launch(void* const* d_in, const int* in_sizes, int n_in,
                              void* d_out, int out_size) {
    const int*   obj_id = (const int*)  d_in[0];
    const float* cam_K  = (const float*)d_in[1];
    const float* gtR    = (const float*)d_in[2];
    const float* gtT    = (const float*)d_in[3];
    const float* prR    = (const float*)d_in[4];
    const float* prT    = (const float*)d_in[5];
    const float* coord  = (const float*)d_in[6];
    const unsigned int* maskp = (const unsigned int*)d_in[7];
    const float* mesh   = (const float*)d_in[8];
    const float* diam   = (const float*)d_in[9];
    float* out = (float*)d_out;

    cudaFuncSetAttribute(score_kernel, cudaFuncAttributeMaxDynamicSharedMemorySize, DYN_SMEM);
    score_kernel<<<2 * NS, TPB, DYN_SMEM>>>(obj_id, cam_K, gtR, gtT, prR, prT,
                                            coord, maskp, mesh, diam, out);
}